// round 6
// baseline (speedup 1.0000x reference)
#include <cuda_runtime.h>
#include <cstdint>

// LocalExpansion, double-buffered SMEM staging + bulk async stores (UBLKCP).
// Each CTA produces 8 chunks of 2 output pixel-rows (25088 B each, contiguous
// in gmem). Two SMEM buffers: fill buf B while the bulk engine drains buf A
// (cp.async.bulk.wait_group.read 1 gives backpressure). Input is tiny (2.4 MB)
// and L1/L2-hot, so fills are cheap; the goal is to keep the bulk write queue
// continuously fed.
//
// B*H = 16, N = 48*48 = 2304, K = 49, D = 64 floats (= 16 float4).

#define HEIGHT 48
#define WIDTH  48
#define NPIX   (HEIGHT * WIDTH)          // 2304
#define KK     49
#define DVEC   16                        // float4 per tap
#define CHUNK_PIX 2
#define CHUNK_ELEMS (CHUNK_PIX * KK * DVEC)  // 1568 float4
#define CHUNK_BYTES (CHUNK_ELEMS * 16)       // 25088
#define CHUNKS_PER_CTA 8
#define THREADS 256

__global__ void __launch_bounds__(THREADS) local_expand_pipe_kernel(
    const float4* __restrict__ in, float4* __restrict__ out)
{
    __shared__ alignas(128) float4 buf[2][CHUNK_ELEMS];

    const unsigned int chunk0 = blockIdx.x * CHUNKS_PER_CTA;

    #pragma unroll 1
    for (int c = 0; c < CHUNKS_PER_CTA; ++c) {
        const int b = c & 1;

        if (c >= 2) {
            // buffer b is reused: make sure its previous bulk store has been READ
            if (threadIdx.x == 0)
                asm volatile("cp.async.bulk.wait_group.read 1;" ::: "memory");
            __syncthreads();
        }

        const unsigned int p0 = (chunk0 + (unsigned)c) * CHUNK_PIX;

        #pragma unroll
        for (int it = 0; it < (CHUNK_ELEMS + THREADS - 1) / THREADS; ++it) {
            unsigned int idx = threadIdx.x + it * THREADS;
            if (idx < CHUNK_ELEMS) {
                unsigned int dv = idx & (DVEC - 1);
                unsigned int r  = idx >> 4;               // pp*49 + k, r < 98
                unsigned int pp = (r >= KK) ? 1u : 0u;    // no div needed
                unsigned int k  = r - KK * pp;
                unsigned int p  = p0 + pp;
                unsigned int n  = p % NPIX;
                int y = (int)(n / WIDTH);
                int x = (int)(n % WIDTH);
                int i = (int)(k / 7);
                int j = (int)(k % 7);
                int sy = y + i - 3;
                int sx = x + j - 3;

                float4 v = make_float4(0.f, 0.f, 0.f, 0.f);
                if ((unsigned)sy < (unsigned)HEIGHT && (unsigned)sx < (unsigned)WIDTH) {
                    // (p - n) = bh * NPIX
                    v = __ldg(in + ((size_t)(p - n) + (unsigned)(sy * WIDTH + sx)) * DVEC + dv);
                }
                buf[b][idx] = v;
            }
        }

        asm volatile("fence.proxy.async.shared::cta;" ::: "memory");
        __syncthreads();

        if (threadIdx.x == 0) {
            uint32_t saddr;
            asm("{ .reg .u64 t; cvta.to.shared.u64 t, %1; cvt.u32.u64 %0, t; }"
                : "=r"(saddr) : "l"(&buf[b][0]));
            const float4* dst = out + (size_t)p0 * (KK * DVEC);
            asm volatile("cp.async.bulk.global.shared::cta.bulk_group [%0], [%1], %2;"
                :: "l"(dst), "r"(saddr), "r"((unsigned)CHUNK_BYTES) : "memory");
            asm volatile("cp.async.bulk.commit_group;" ::: "memory");
        }
    }

    // CTA must not exit while the bulk engine still reads its SMEM
    if (threadIdx.x == 0)
        asm volatile("cp.async.bulk.wait_group.read 0;" ::: "memory");
}

extern "C" void kernel_launch(void* const* d_in, const int* in_sizes, int n_in,
                              void* d_out, int out_size)
{
    const float4* in = (const float4*)d_in[0];
    float4* out = (float4*)d_out;

    // total pixels = out floats / (49*64) = 36864
    unsigned int npix_total = (unsigned int)(out_size / (KK * 64));
    unsigned int blocks = npix_total / (CHUNK_PIX * CHUNKS_PER_CTA);  // 2304
    local_expand_pipe_kernel<<<blocks, THREADS>>>(in, out);
}

// round 7
// speedup vs baseline: 1.0669x; 1.0669x over previous
#include <cuda_runtime.h>

// LocalExpansion via scatter, final form.
// out[q, k, dv] = in[q + shift(k), dv] (7x7 window, zero-padded).
// Thread (bh, y, x, dv) loads its own 16B slice once, then scatters it to the
// 49 destinations q = p - shift(k) and zero-fills its own row's OOB taps.
// 3D grid supplies (x, y, bh) directly -> zero index arithmetic.
// Interior pixels (76%) take a predicate-free 49-store path (max store MLP).
//
// B*H = 16, N = 48*48 = 2304, K = 49, D = 64 floats (= 16 float4).

#define HEIGHT 48
#define WIDTH  48
#define NPIX   (HEIGHT * WIDTH)   // 2304
#define KK     49
#define DVEC   16                 // float4 per tap
#define ROWV   (KK * DVEC)        // 784 float4 per output pixel row

__global__ void __launch_bounds__(256) local_scatter_final_kernel(
    const float4* __restrict__ in, float4* __restrict__ out)
{
    // blockDim = 256 = 16 dv * 16 x-pixels ; gridDim = (3, 48, 16)
    const int dv = (int)(threadIdx.x & 15u);
    const int x  = (int)(blockIdx.x * 16u + (threadIdx.x >> 4));
    const int y  = (int)blockIdx.y;
    const int bh = (int)blockIdx.z;

    const unsigned int p = (unsigned)bh * NPIX + (unsigned)(y * WIDTH + x);

    const float4 v = __ldg(in + (size_t)p * DVEC + dv);
    float4* __restrict__ base = out + (size_t)p * ROWV + dv;

    if ((unsigned)(y - 3) < (unsigned)(HEIGHT - 6) &&
        (unsigned)(x - 3) < (unsigned)(WIDTH - 6)) {
        // Interior: all 49 source and destination pixels valid.
        #pragma unroll
        for (int i = 0; i < 7; ++i) {
            #pragma unroll
            for (int j = 0; j < 7; ++j) {
                const int k = i * 7 + j;
                const int scat_off = -(((i - 3) * WIDTH) + (j - 3)) * ROWV + k * DVEC;
                __stcs(base + scat_off, v);
            }
        }
    } else {
        const float4 z = make_float4(0.f, 0.f, 0.f, 0.f);
        #pragma unroll
        for (int i = 0; i < 7; ++i) {
            const bool src_yok = (unsigned)(y + (i - 3)) < (unsigned)HEIGHT;
            const bool dst_yok = (unsigned)(y - (i - 3)) < (unsigned)HEIGHT;
            #pragma unroll
            for (int j = 0; j < 7; ++j) {
                const int k = i * 7 + j;
                const bool dst_ok = dst_yok && ((unsigned)(x - (j - 3)) < (unsigned)WIDTH);
                const bool src_ok = src_yok && ((unsigned)(x + (j - 3)) < (unsigned)WIDTH);

                const int scat_off = -(((i - 3) * WIDTH) + (j - 3)) * ROWV + k * DVEC;
                if (dst_ok) __stcs(base + scat_off, v);      // scatter my value
                if (!src_ok) __stcs(base + k * DVEC, z);     // zero-fill my OOB tap
            }
        }
    }
}

extern "C" void kernel_launch(void* const* d_in, const int* in_sizes, int n_in,
                              void* d_out, int out_size)
{
    const float4* in = (const float4*)d_in[0];
    float4* out = (float4*)d_out;
    (void)out_size;

    dim3 grid(WIDTH / 16, HEIGHT, 16);   // (3, 48, 16) -> 2304 CTAs
    local_scatter_final_kernel<<<grid, 256>>>(in, out);
}